// round 15
// baseline (speedup 1.0000x reference)
#include <cuda_runtime.h>
#include <cuda_bf16.h>
#include <cuda_fp16.h>
#include <cstdint>
#include <math.h>

#define BATCH   128
#define LATENT  256
#define HIDDEN  512
#define NODE_F  128
#define MAXN    50
#define E_TOTAL 1225
#define KDIM    512
#define N2      256
#define NODE_OUT (BATCH * MAXN * NODE_F)
#define MROWS   (BATCH * MAXN)          // 6400

// ------------------------- device scratch (no allocs) -----------------------
__device__ __nv_bfloat16 g_zh[BATCH * LATENT],   g_zl[BATCH * LATENT];
__device__ __nv_bfloat16 g_W1h[1024 * LATENT],   g_W1l[1024 * LATENT]; // [nw1^T; ew1z^T]
__device__ __nv_bfloat16 g_W2h[HIDDEN * HIDDEN], g_W2l[HIDDEN * HIDDEN];
__device__ __nv_bfloat16 g_W3h[MROWS * HIDDEN],  g_W3l[MROWS * HIDDEN];
__device__ __nv_bfloat16 g_h1h[BATCH * HIDDEN],  g_h1l[BATCH * HIDDEN];
__device__ __nv_bfloat16 g_h2h[BATCH * HIDDEN],  g_h2l[BATCH * HIDDEN];
__device__ __half g_Wp16[2 * KDIM * NODE_F];     // ew1 Wi/Wj ^T fp16 [1024][128]
__device__ __half g_nf16[MROWS * NODE_F];        // nf fp16 [6400][128]
__device__ float  g_R [BATCH * KDIM];
__device__ __half g_Ph[MROWS * KDIM];            // fp16 P = nf@Wi + R
__device__ __half g_Qh[MROWS * KDIM];            // fp16 Q = nf@Wj
__device__ int2   g_edge[E_TOTAL];
__device__ __half g_Bh[N2 * KDIM];               // ew2^T fp16 [256 n][512 k]

// ------------------------- helpers ------------------------------------------
__device__ __forceinline__ uint32_t smem_u32(const void* p) {
    uint32_t a;
    asm("{ .reg .u64 t; cvta.to.shared.u64 t, %1; cvt.u32.u64 %0, t; }"
        : "=r"(a) : "l"(p));
    return a;
}
__device__ __forceinline__ void mma16816_f16(float* c, const uint32_t* a,
                                             uint32_t b0, uint32_t b1) {
    asm volatile(
        "mma.sync.aligned.m16n8k16.row.col.f32.f16.f16.f32 "
        "{%0,%1,%2,%3}, {%4,%5,%6,%7}, {%8,%9}, {%0,%1,%2,%3};"
        : "+f"(c[0]), "+f"(c[1]), "+f"(c[2]), "+f"(c[3])
        : "r"(a[0]), "r"(a[1]), "r"(a[2]), "r"(a[3]), "r"(b0), "r"(b1));
}
__device__ __forceinline__ void mma16816_bf(float* c, const uint32_t* a,
                                            uint32_t b0, uint32_t b1) {
    asm volatile(
        "mma.sync.aligned.m16n8k16.row.col.f32.bf16.bf16.f32 "
        "{%0,%1,%2,%3}, {%4,%5,%6,%7}, {%8,%9}, {%0,%1,%2,%3};"
        : "+f"(c[0]), "+f"(c[1]), "+f"(c[2]), "+f"(c[3])
        : "r"(a[0]), "r"(a[1]), "r"(a[2]), "r"(a[3]), "r"(b0), "r"(b1));
}
#define LDM4(r, addr) \
    asm volatile("ldmatrix.sync.aligned.m8n8.x4.shared.b16 {%0,%1,%2,%3}, [%4];" \
        : "=r"((r)[0]), "=r"((r)[1]), "=r"((r)[2]), "=r"((r)[3]) : "r"(addr))
#define CP_ASYNC16(dst, src) \
    asm volatile("cp.async.cg.shared.global [%0], [%1], 16;" \
                 :: "r"(dst), "l"(src) : "memory")
#define CP_COMMIT()  asm volatile("cp.async.commit_group;" ::: "memory")
#define CP_WAIT0()   asm volatile("cp.async.wait_group 0;" ::: "memory")
#define CP_WAIT1()   asm volatile("cp.async.wait_group 1;" ::: "memory")
#define CP_WAIT2()   asm volatile("cp.async.wait_group 2;" ::: "memory")

__device__ __forceinline__ void bf16_split(float v, __nv_bfloat16& h, __nv_bfloat16& l) {
    h = __float2bfloat16(v);
    l = __float2bfloat16(v - __bfloat162float(h));
}

// ---------------------------------------------------------------------------
// Prep bodies (64k x 32n coalesced transpose tiles)
// ---------------------------------------------------------------------------
__device__ __forceinline__ void tsplit_body(const float* __restrict__ src,
                                            __nv_bfloat16* __restrict__ dh,
                                            __nv_bfloat16* __restrict__ dl,
                                            int K, int N, int t, int kt,
                                            float (*sh)[33]) {
    const int k0 = (t % kt) * 64;
    const int n0 = (t / kt) * 32;
    const int tx = threadIdx.x & 31;
    const int ty = threadIdx.x >> 5;
#pragma unroll
    for (int r = ty; r < 64; r += 8)
        sh[r][tx] = src[(size_t)(k0 + r) * N + n0 + tx];
    __syncthreads();
#pragma unroll
    for (int r = ty; r < 32; r += 8) {
        float v0 = sh[2 * tx][r], v1 = sh[2 * tx + 1][r];
        __nv_bfloat16 h0, l0, h1, l1;
        bf16_split(v0, h0, l0); bf16_split(v1, h1, l1);
        const size_t o = ((size_t)(n0 + r) * K + k0 + 2 * tx) >> 1;
        ((__nv_bfloat162*)dh)[o] = __nv_bfloat162(h0, h1);
        ((__nv_bfloat162*)dl)[o] = __nv_bfloat162(l0, l1);
    }
}
__device__ __forceinline__ void tsplit_h_body(const float* __restrict__ src,
                                              __half* __restrict__ dst,
                                              int K, int N, int t, int kt,
                                              float (*sh)[33]) {
    const int k0 = (t % kt) * 64;
    const int n0 = (t / kt) * 32;
    const int tx = threadIdx.x & 31;
    const int ty = threadIdx.x >> 5;
#pragma unroll
    for (int r = ty; r < 64; r += 8)
        sh[r][tx] = src[(size_t)(k0 + r) * N + n0 + tx];
    __syncthreads();
#pragma unroll
    for (int r = ty; r < 32; r += 8) {
        float v0 = sh[2 * tx][r], v1 = sh[2 * tx + 1][r];
        const size_t o = ((size_t)(n0 + r) * K + k0 + 2 * tx) >> 1;
        ((__half2*)dst)[o] = __floats2half2_rn(v0, v1);
    }
}

// side stream: W3 transpose (1600 blocks)
__global__ __launch_bounds__(256)
void prep_W3_kernel(const float* __restrict__ nw3) {
    __shared__ float sh[64][33];
    tsplit_body(nw3, g_W3h, g_W3l, 512, 6400, blockIdx.x, 8, sh);
}

// side stream: B + Wp (needed only from pq/edge onward) — 128 blocks
__global__ __launch_bounds__(256)
void prep_bwp_kernel(const float* __restrict__ ew1, const float* __restrict__ ew2) {
    __shared__ float sh[64][33];
    int bid = blockIdx.x;
    if (bid < 64) { tsplit_h_body(ew2, g_Bh, 512, 256, bid, 8, sh); return; }
    bid -= 64;
    if (bid < 32) { tsplit_h_body(ew1 + 256 * 512, g_Wp16, 128, 512, bid, 2, sh); return; }
    bid -= 32;
    { tsplit_h_body(ew1 + 384 * 512, g_Wp16 + 512 * 128, 128, 512, bid, 2, sh); }
}

// main stream: W2, W1 parts, z, edge table — 389 blocks (lin1R/lin2 deps only)
#define PREPF_BLOCKS (128 + 64 + 64 + 128 + 5)

__global__ __launch_bounds__(256)
void prep_front_kernel(const float* __restrict__ nw2, const float* __restrict__ nw1,
                       const float* __restrict__ ew1, const float* __restrict__ z) {
    __shared__ float sh[64][33];
    int bid = blockIdx.x;
    if (bid < 128)  { tsplit_body(nw2, g_W2h, g_W2l, 512, 512, bid, 8, sh); return; }
    bid -= 128;
    if (bid < 64)   { tsplit_body(nw1, g_W1h, g_W1l, 256, 512, bid, 4, sh); return; }
    bid -= 64;
    if (bid < 64)   { tsplit_body(ew1, g_W1h + 512 * 256, g_W1l + 512 * 256,
                                  256, 512, bid, 4, sh); return; }
    bid -= 64;
    if (bid < 128) {
        const int idx = bid * 256 + threadIdx.x;
        __nv_bfloat16 h, l; bf16_split(z[idx], h, l);
        g_zh[idx] = h; g_zl[idx] = l;
        return;
    }
    bid -= 128;
    {
        const int e = bid * 256 + threadIdx.x;
        if (e < E_TOTAL) {
            int rem = e, i = 0, cnt = MAXN - 1;
            while (rem >= cnt) { rem -= cnt; cnt--; i++; }
            g_edge[e] = make_int2(i, i + 1 + rem);
        }
    }
}

// ---------------------------------------------------------------------------
// 3-pass bf16 split GEMM, 4-DEEP cp.async pipeline, MT x NT tiles.
// C[MT m, NT n] = A[m][K] @ B[n][K]^T.  8 warps = 4 mg x 2 ng.
// EPI 0 (nw3): +nb3; node sigmoid -> out; nf -> fp16.
// EPI 2 (lin1+R): n<512: relu(C+nb1)->h1 split; else C+eb1 -> g_R.
// EPI 3 (lin2): relu(C+nb2)->h2 split.
// ---------------------------------------------------------------------------
template<int K, int EPI, int MT, int NT>
__global__ __launch_bounds__(256)
void gemm3p_kernel(const __nv_bfloat16* __restrict__ Ahi,
                   const __nv_bfloat16* __restrict__ Alo,
                   const __nv_bfloat16* __restrict__ Bhi,
                   const __nv_bfloat16* __restrict__ Blo,
                   const float* __restrict__ bias,
                   const float* __restrict__ bias2,
                   float* __restrict__ out_nodes) {
    extern __shared__ char sm[];
    const uint32_t sb = smem_u32(sm);
    constexpr int NCH  = K / 64;
    constexpr int WNT  = NT / 2;
    constexpr int NBL  = WNT / 16;
    constexpr int MF   = MT / 64;
    constexpr int MGR  = MT / 4;
    constexpr int BHIO = 2 * MT * 144;
    constexpr int BLOO = BHIO + NT * 144;
    constexpr int BUF  = BHIO + 2 * NT * 144;

    const int tid = threadIdx.x, lane = tid & 31, wid = tid >> 5;
    const int g = lane >> 2, qi = lane & 3;
    const int mg = wid >> 1, ng = wid & 1;
    const int m0 = blockIdx.x * MT, n0 = blockIdx.y * NT;

    const uint32_t aHiB = sb + (uint32_t)(mg * MGR + (lane & 15)) * 144
                        + (lane >> 4) * 16;
    const uint32_t aLoB = aHiB + MT * 144;
    const int brow = ng * WNT + ((lane >> 4) & 1) * 8 + (lane & 7);
    const uint32_t bHiB = sb + BHIO + (uint32_t)brow * 144 + ((lane >> 3) & 1) * 16;
    const uint32_t bLoB = bHiB + (BLOO - BHIO);

    auto stage = [&](int c, int buf) {
        const uint32_t bb = sb + buf * BUF;
#pragma unroll
        for (int p = tid; p < MT * 8; p += 256) {
            const int r = p >> 3, pc = p & 7;
            const size_t so = ((size_t)(m0 + r) * K + c * 64) * 2 + pc * 16;
            CP_ASYNC16(bb + r * 144 + pc * 16,            (const char*)Ahi + so);
            CP_ASYNC16(bb + MT * 144 + r * 144 + pc * 16, (const char*)Alo + so);
        }
#pragma unroll
        for (int p = tid; p < NT * 8; p += 256) {
            const int r = p >> 3, pc = p & 7;
            const size_t so = ((size_t)(n0 + r) * K + c * 64) * 2 + pc * 16;
            CP_ASYNC16(bb + BHIO + r * 144 + pc * 16, (const char*)Bhi + so);
            CP_ASYNC16(bb + BLOO + r * 144 + pc * 16, (const char*)Blo + so);
        }
    };

    float acc[MF][2 * NBL][4];
#pragma unroll
    for (int a = 0; a < MF; a++)
#pragma unroll
        for (int b2 = 0; b2 < 2 * NBL; b2++)
#pragma unroll
            for (int u = 0; u < 4; u++) acc[a][b2][u] = 0.0f;

    // prologue: 3 chunks in flight
#pragma unroll
    for (int i = 0; i < 3; i++) {
        stage(i, i);
        CP_COMMIT();
    }

    for (int c = 0; c < NCH; c++) {
        // wait for chunk c (tail-aware immediates)
        const int rem = NCH - 1 - c;
        if (rem >= 2) CP_WAIT2();
        else if (rem == 1) CP_WAIT1();
        else CP_WAIT0();
        __syncthreads();                   // all threads done with MMA(c-1)
        if (c + 3 < NCH) {                 // stage into buffer (c-1)&3 — now safe
            stage(c + 3, (c + 3) & 3);
            CP_COMMIT();
        }
        const uint32_t off = (uint32_t)(c & 3) * BUF;
#pragma unroll
        for (int ks = 0; ks < 4; ks++) {
            uint32_t ah[MF][4], al[MF][4];
#pragma unroll
            for (int mf = 0; mf < MF; mf++) {
                LDM4(ah[mf], aHiB + off + mf * (16 * 144) + ks * 32);
                LDM4(al[mf], aLoB + off + mf * (16 * 144) + ks * 32);
            }
#pragma unroll
            for (int nbl = 0; nbl < NBL; nbl++) {
                uint32_t bh[4], bl[4];
                LDM4(bh, bHiB + off + nbl * (16 * 144) + ks * 32);
                LDM4(bl, bLoB + off + nbl * (16 * 144) + ks * 32);
#pragma unroll
                for (int mf = 0; mf < MF; mf++) {
                    float* c0 = acc[mf][2 * nbl];
                    float* c1 = acc[mf][2 * nbl + 1];
                    mma16816_bf(c0, ah[mf], bh[0], bh[1]);
                    mma16816_bf(c1, ah[mf], bh[2], bh[3]);
                    mma16816_bf(c0, al[mf], bh[0], bh[1]);
                    mma16816_bf(c1, al[mf], bh[2], bh[3]);
                    mma16816_bf(c0, ah[mf], bl[0], bl[1]);
                    mma16816_bf(c1, ah[mf], bl[2], bl[3]);
                }
            }
        }
    }

#pragma unroll
    for (int mf = 0; mf < MF; mf++)
#pragma unroll
        for (int nb = 0; nb < 2 * NBL; nb++)
#pragma unroll
            for (int u = 0; u < 4; u++) {
                const int row = mg * MGR + mf * 16 + g + (u >> 1) * 8;
                const int col = ng * WNT + nb * 8 + qi * 2 + (u & 1);
                const int mG = m0 + row, nG = n0 + col;
                float v = acc[mf][nb][u];
                if (EPI == 0) {                       // nw3
                    v += bias[nG];
                    const int node = nG >> 7, f = nG & 127;
                    g_nf16[((size_t)mG * MAXN + node) * NODE_F + f] = __float2half_rn(v);
                    out_nodes[(size_t)mG * 6400 + nG] = 1.0f / (1.0f + expf(-v));
                } else if (EPI == 2) {                // lin1 + R
                    if (nG < 512) {
                        v = fmaxf(v + bias[nG], 0.0f);
                        __nv_bfloat16 h, l; bf16_split(v, h, l);
                        g_h1h[(size_t)mG * 512 + nG] = h;
                        g_h1l[(size_t)mG * 512 + nG] = l;
                    } else {
                        g_R[(size_t)mG * 512 + nG - 512] = v + bias2[nG - 512];
                    }
                } else {                              // lin2
                    v = fmaxf(v + bias[nG], 0.0f);
                    __nv_bfloat16 h, l; bf16_split(v, h, l);
                    g_h2h[(size_t)mG * 512 + nG] = h;
                    g_h2l[(size_t)mG * 512 + nG] = l;
                }
            }
}

// ---------------------------------------------------------------------------
// Single-pass fp16 GEMM for P/Q, double-buffered (2 chunks total). Grid (50,16).
// ---------------------------------------------------------------------------
#define G1_A   0
#define G1_B   18432
#define G1_BUF 27648
#define G1_TOT 55296

__global__ __launch_bounds__(256)
void gemm1p_kernel() {
    extern __shared__ char sm[];
    const uint32_t sb = smem_u32(sm);
    const int tid = threadIdx.x, lane = tid & 31, wid = tid >> 5;
    const int g = lane >> 2, qi = lane & 3;
    const int mg = wid >> 1, ng = wid & 1;
    const int m0 = blockIdx.x * 128, n0 = blockIdx.y * 64;

    const uint32_t aAB = sb + G1_A + (uint32_t)(mg * 32 + (lane & 15)) * 144
                       + (lane >> 4) * 16;
    const int brow = ng * 32 + ((lane >> 4) & 1) * 8 + (lane & 7);
    const uint32_t aBB = sb + G1_B + (uint32_t)brow * 144 + ((lane >> 3) & 1) * 16;

    auto stage = [&](int c, int buf) {
        const uint32_t bb = sb + buf * G1_BUF;
#pragma unroll
        for (int p = tid; p < 1024; p += 256) {
            const int r = p >> 3, pc = p & 7;
            CP_ASYNC16(bb + G1_A + r * 144 + pc * 16,
                       (const char*)g_nf16 + ((size_t)(m0 + r) * 128 + c * 64) * 2 + pc * 16);
        }
#pragma unroll
        for (int p = tid; p < 512; p += 256) {
            const int r = p >> 3, pc = p & 7;
            CP_ASYNC16(bb + G1_B + r * 144 + pc * 16,
                       (const char*)g_Wp16 + ((size_t)(n0 + r) * 128 + c * 64) * 2 + pc * 16);
        }
    };

    float acc[2][4][4];
#pragma unroll
    for (int a = 0; a < 2; a++)
#pragma unroll
        for (int b2 = 0; b2 < 4; b2++)
#pragma unroll
            for (int u = 0; u < 4; u++) acc[a][b2][u] = 0.0f;

    stage(0, 0);
    CP_COMMIT();
    stage(1, 1);
    CP_COMMIT();

    for (int c = 0; c < 2; c++) {
        if (c == 0) CP_WAIT1(); else CP_WAIT0();
        __syncthreads();
        const uint32_t off = (uint32_t)(c & 1) * G1_BUF;
#pragma unroll
        for (int ks = 0; ks < 4; ks++) {
            uint32_t a0[4], a1[4];
            LDM4(a0, aAB + off + ks * 32);
            LDM4(a1, aAB + off + 16 * 144 + ks * 32);
#pragma unroll
            for (int nb = 0; nb < 2; nb++) {
                uint32_t bh[4];
                LDM4(bh, aBB + off + nb * (16 * 144) + ks * 32);
                mma16816_f16(acc[0][2 * nb],     a0, bh[0], bh[1]);
                mma16816_f16(acc[1][2 * nb],     a1, bh[0], bh[1]);
                mma16816_f16(acc[0][2 * nb + 1], a0, bh[2], bh[3]);
                mma16816_f16(acc[1][2 * nb + 1], a1, bh[2], bh[3]);
            }
        }
    }

#pragma unroll
    for (int mf = 0; mf < 2; mf++)
#pragma unroll
        for (int nb = 0; nb < 4; nb++)
#pragma unroll
            for (int u = 0; u < 4; u++) {
                const int row = mg * 32 + mf * 16 + g + (u >> 1) * 8;
                const int col = ng * 32 + nb * 8 + qi * 2 + (u & 1);
                const int mG = m0 + row, n2 = n0 + col;
                float v = acc[mf][nb][u];
                const int mat = n2 >> 9, nc = n2 & 511;
                if (!mat) {
                    v += g_R[(size_t)(mG / MAXN) * KDIM + nc];
                    g_Ph[(size_t)mG * KDIM + nc] = __float2half_rn(v);
                } else {
                    g_Qh[(size_t)mG * KDIM + nc] = __float2half_rn(v);
                }
            }
}

// ---------------------------------------------------------------------------
// Edge kernel (unchanged): e1 = relu(P_i + Q_j) fp16; single-pass fp16 HMMA.
// ---------------------------------------------------------------------------
#define BN_STRIDE 144
#define PQ_STRIDE 144
#define BBUF_SZ   36864
#define OFF_P     73728            // + buf*14400 ; Q at +7200
#define PQBUF_SZ  14400
#define OFF_AHI   102528
#define OFF_EB2   120960
#define OFF_EW3   121984
#define OFF_RED   123008
#define EDGE_SMEM 125056

__device__ __forceinline__ void stage_B(uint32_t sb, int c, int bufoff, int tid) {
    const uint32_t base = sb + bufoff;
#pragma unroll
    for (int p = tid; p < 2048; p += 512) {
        const int r  = p >> 3;
        const int pc = p & 7;
        const char* src = (const char*)g_Bh + r * 1024 + c * 128 + pc * 16;
        CP_ASYNC16(base + r * BN_STRIDE + pc * 16, src);
    }
}
__device__ __forceinline__ void stage_PQ(uint32_t sb, int b, int c, int buf, int tid) {
    for (int p = tid; p < 800; p += 512) {
        const int mat = p >= 400;
        const int s2  = p - mat * 400;
        const int r   = s2 >> 3;
        const int pc  = s2 & 7;
        const char* src = (const char*)(mat ? g_Qh : g_Ph)
                        + (size_t)(b * MAXN + r) * 1024 + c * 128 + pc * 16;
        CP_ASYNC16(sb + OFF_P + buf * PQBUF_SZ + mat * 7200 + r * PQ_STRIDE + pc * 16,
                   src);
    }
}

__global__ __launch_bounds__(512, 1)
void edge_mma_kernel(const float* __restrict__ eb2g,
                     const float* __restrict__ ew3g,
                     const float* __restrict__ eb3g,
                     float* __restrict__ out_edges) {
    extern __shared__ char sm[];
    const uint32_t sb = smem_u32(sm);
    const int tid  = threadIdx.x;
    const int lane = tid & 31, wid = tid >> 5;
    const int g    = lane >> 2, qi = lane & 3;
    const int mg   = wid >> 2,  ng = wid & 3;
    const int b      = blockIdx.y;
    const int e_base = blockIdx.x * 128;

    if (tid < 256) {
        ((float*)(sm + OFF_EB2))[tid] = eb2g[tid];
        ((float*)(sm + OFF_EW3))[tid] = ew3g[tid];
    }

    const int mb = tid >> 2;
    const int kk = (tid & 3) * 16;
    const int2 ijb = g_edge[min(e_base + mb, E_TOTAL - 1)];
    const int pOff = ijb.x * PQ_STRIDE + kk * 2;
    const int qOff = 7200 + ijb.y * PQ_STRIDE + kk * 2;
    char* ahiW = sm + OFF_AHI + mb * BN_STRIDE + kk * 2;

    const uint32_t aoff = (uint32_t)(mg * 32 + (lane & 15)) * BN_STRIDE
                        + (uint32_t)(lane >> 4) * 16;
    const uint32_t aHi = sb + OFF_AHI + aoff;
    const int brow  = ng * 64 + ((lane >> 4) & 1) * 8 + (lane & 7);
    const uint32_t boff = (uint32_t)brow * BN_STRIDE + ((lane >> 3) & 1) * 16;

    stage_B(sb, 0, 0, tid);
    stage_PQ(sb, b, 0, 0, tid);
    CP_COMMIT();

    float acc[2][8][4];
#pragma unroll
    for (int mt = 0; mt < 2; mt++)
#pragma unroll
        for (int f = 0; f < 8; f++)
#pragma unroll
            for (int u = 0; u < 4; u++) acc[mt][f][u] = 0.0f;

    for (int c = 0; c < 8; c++) {
        CP_WAIT0();
        __syncthreads();

        if (c + 1 < 8) {
            stage_B(sb, c + 1, ((c + 1) & 1) * BBUF_SZ, tid);
            stage_PQ(sb, b, c + 1, (c + 1) & 1, tid);
            CP_COMMIT();
        }

        {
            const char* base = sm + OFF_P + (c & 1) * PQBUF_SZ;
            const uint4 pa = *(const uint4*)(base + pOff);
            const uint4 pb2 = *(const uint4*)(base + pOff + 16);
            const uint4 qa = *(const uint4*)(base + qOff);
            const uint4 qb2 = *(const uint4*)(base + qOff + 16);
            const __half2 z2 = __float2half2_rn(0.0f);
            uint32_t pw[8] = {pa.x, pa.y, pa.z, pa.w, pb2.x, pb2.y, pb2.z, pb2.w};
            uint32_t qw[8] = {qa.x, qa.y, qa.z, qa.w, qb2.x, qb2.y, qb2.z, qb2.w};
            uint32_t o[8];
#pragma unroll
            for (int x = 0; x < 8; x++) {
                __half2 r = __hmax2(__hadd2(*(__half2*)&pw[x], *(__half2*)&qw[x]), z2);
                o[x] = *(uint32_t*)&r;
            }
            *(uint4*)(ahiW)      = make_uint4(o[0], o[1], o[2], o[3]);
            *(uint4*)(ahiW + 16) = make_uint4(o[4], o[5], o[6], o[7]);
        }
        __syncthreads();

        const uint32_t bbase = sb + (c & 1) * BBUF_SZ + boff;
#pragma unroll
        for (int ks = 0; ks < 4; ks++) {
            uint32_t a0[4], a1[4];
            LDM4(a0, aHi + ks * 32);
            LDM4(a1, aHi + 16 * BN_STRIDE + ks * 32);
#pragma unroll
            for (int fp = 0; fp < 4; fp++) {
                uint32_t bh[4];
                LDM4(bh, bbase + fp * (16 * BN_STRIDE) + ks * 32);
                mma16816_f16(acc[0][2*fp],   a0, bh[0], bh[1]);
                mma16816_f16(acc[1][2*fp],   a1, bh[0], bh[1]);
                mma16816_f16(acc[0][2*fp+1], a0, bh[2], bh[3]);
                mma16816_f16(acc[1][2*fp+1], a1, bh[2], bh[3]);
            }
        }
    }

    const float* eb2s = (const float*)(sm + OFF_EB2);
    const float* ew3s = (const float*)(sm + OFF_EW3);
    int rowm[4];
    rowm[0] = mg * 32 + g;      rowm[1] = mg * 32 + 8 + g;
    rowm[2] = mg * 32 + 16 + g; rowm[3] = mg * 32 + 24 + g;
    float pr[4] = {0.f, 0.f, 0.f, 0.f};
#pragma unroll
    for (int f = 0; f < 8; f++) {
        const int n0 = ng * 64 + f * 8 + qi * 2;
        const float b0 = eb2s[n0], b1 = eb2s[n0 + 1];
        const float w0 = ew3s[n0], w1 = ew3s[n0 + 1];
#pragma unroll
        for (int mt = 0; mt < 2; mt++) {
            pr[mt * 2 + 0] += fmaxf(acc[mt][f][0] + b0, 0.0f) * w0 +
                              fmaxf(acc[mt][f][1] + b1, 0.0f) * w1;
            pr[mt * 2 + 1] += fmaxf(acc[mt][f][2] + b0, 0.0f) * w0 +
                              fmaxf(acc[mt][f][3] + b1, 0.0f) * w1;
        }
    }
#pragma unroll
    for (int j = 0; j < 4; j++) {
        pr[j] += __shfl_xor_sync(0xffffffffu, pr[j], 1);
        pr[j] += __shfl_xor_sync(0xffffffffu, pr[j], 2);
    }
    float* red = (float*)(sm + OFF_RED);
    if (qi == 0) {
#pragma unroll
        for (int j = 0; j < 4; j++) red[ng * 128 + rowm[j]] = pr[j];
    }
    __syncthreads();
    if (tid < 128) {
        int e = e_base + tid;
        if (e < E_TOTAL) {
            float s = red[tid] + red[128 + tid] + red[256 + tid] + red[384 + tid]
                    + eb3g[0];
            out_edges[(size_t)b * E_TOTAL + e] = 1.0f / (1.0f + expf(-s));
        }
    }
}

// ---------------------------------------------------------------------------
extern "C" void kernel_launch(void* const* d_in, const int* in_sizes, int n_in,
                              void* d_out, int out_size) {
    const float* z   = (const float*)d_in[0];
    const float* nw1 = (const float*)d_in[1];
    const float* nb1 = (const float*)d_in[2];
    const float* nw2 = (const float*)d_in[3];
    const float* nb2 = (const float*)d_in[4];
    const float* nw3 = (const float*)d_in[5];
    const float* nb3 = (const float*)d_in[6];
    const float* ew1 = (const float*)d_in[7];
    const float* eb1 = (const float*)d_in[8];
    const float* ew2 = (const float*)d_in[9];
    const float* eb2 = (const float*)d_in[10];
    const float* ew3 = (const float*)d_in[11];
    const float* eb3 = (const float*)d_in[12];

    float* out_nodes = (float*)d_out;
    float* out_edges = (float*)d_out + NODE_OUT;

    __nv_bfloat16 *zh, *zl, *W1h, *W1l, *W2h, *W2l, *W3h, *W3l;
    __nv_bfloat16 *h1h, *h1l, *h2h, *h2l;
    cudaGetSymbolAddress((void**)&zh,  g_zh);  cudaGetSymbolAddress((void**)&zl,  g_zl);
    cudaGetSymbolAddress((void**)&W1h, g_W1h); cudaGetSymbolAddress((void**)&W1l, g_W1l);
    cudaGetSymbolAddress((void**)&W2h, g_W2h); cudaGetSymbolAddress((void**)&W2l, g_W2l);
    cudaGetSymbolAddress((void**)&W3h, g_W3h); cudaGetSymbolAddress((void**)&W3l, g_W3l);
    cudaGetSymbolAddress((void**)&h1h, g_h1h); cudaGetSymbolAddress((void**)&h1l, g_h1l);
    cudaGetSymbolAddress((void**)&h2h, g_h2h); cudaGetSymbolAddress((void**)&h2l, g_h2l);

    constexpr int GS_M64  = 4 * (2 * 64 * 144 + 2 * 32 * 144);   // 110592
    constexpr int GS_M128 = 4 * (2 * 128 * 144 + 2 * 32 * 144);  // 184320

    static bool init_done = false;
    static cudaStream_t s2;
    static cudaEvent_t evFork, evJoin;
    if (!init_done) {
        cudaStreamCreateWithFlags(&s2, cudaStreamNonBlocking);
        cudaEventCreateWithFlags(&evFork, cudaEventDisableTiming);
        cudaEventCreateWithFlags(&evJoin, cudaEventDisableTiming);
        cudaFuncSetAttribute(edge_mma_kernel,
                             cudaFuncAttributeMaxDynamicSharedMemorySize, EDGE_SMEM);
        cudaFuncSetAttribute(gemm3p_kernel<256, 2, 64, 32>,
                             cudaFuncAttributeMaxDynamicSharedMemorySize, GS_M64);
        cudaFuncSetAttribute(gemm3p_kernel<512, 3, 64, 32>,
                             cudaFuncAttributeMaxDynamicSharedMemorySize, GS_M64);
        cudaFuncSetAttribute(gemm3p_kernel<512, 0, 128, 32>,
                             cudaFuncAttributeMaxDynamicSharedMemorySize, GS_M128);
        cudaFuncSetAttribute(gemm1p_kernel,
                             cudaFuncAttributeMaxDynamicSharedMemorySize, G1_TOT);
        init_done = true;
    }

    // fork: W3 + B + Wp transposes on side stream (needed from nw3/pq/edge on)
    cudaEventRecord(evFork, 0);
    cudaStreamWaitEvent(s2, evFork, 0);
    prep_W3_kernel<<<1600, 256, 0, s2>>>(nw3);
    prep_bwp_kernel<<<128, 256, 0, s2>>>(ew1, ew2);
    cudaEventRecord(evJoin, s2);

    // main stream: only lin1R/lin2 deps
    prep_front_kernel<<<PREPF_BLOCKS, 256>>>(nw2, nw1, ew1, z);
    // lin1 + R fused (MT=64 -> 64 CTAs, 4-deep pipeline)
    gemm3p_kernel<256, 2, 64, 32><<<dim3(2, 32), 256, GS_M64>>>(
        zh, zl, W1h, W1l, nb1, eb1, nullptr);
    // lin2 (MT=64 -> 32 CTAs, 4-deep pipeline)
    gemm3p_kernel<512, 3, 64, 32><<<dim3(2, 16), 256, GS_M64>>>(
        h1h, h1l, W2h, W2l, nb2, nullptr, nullptr);

    // join side stream before nw3 (W3) — also covers B/Wp for pq/edge
    cudaStreamWaitEvent(0, evJoin, 0);
    // nf = h2 @ nw3 + nb3 (3-pass bf16, 200 CTAs, 4-deep), node sigmoid, nf fp16
    gemm3p_kernel<512, 0, 128, 32><<<dim3(1, 200), 256, GS_M128>>>(
        h2h, h2l, W3h, W3l, nb3, nullptr, out_nodes);
    // P/Q single-pass fp16 (800 CTAs)
    gemm1p_kernel<<<dim3(MROWS / 128, 16), 256, G1_TOT>>>();

    // dominant edge GEMM (single-pass fp16 HMMA)
    edge_mma_kernel<<<dim3((E_TOTAL + 127) / 128, BATCH), 512, EDGE_SMEM>>>(
        eb2, ew3, eb3, out_edges);
}

// round 17
// speedup vs baseline: 1.0537x; 1.0537x over previous
#include <cuda_runtime.h>
#include <cuda_bf16.h>
#include <cuda_fp16.h>
#include <cstdint>
#include <math.h>

#define BATCH   128
#define LATENT  256
#define HIDDEN  512
#define NODE_F  128
#define MAXN    50
#define E_TOTAL 1225
#define KDIM    512
#define N2      256
#define NODE_OUT (BATCH * MAXN * NODE_F)
#define MROWS   (BATCH * MAXN)          // 6400

// ------------------------- device scratch (no allocs) -----------------------
__device__ __nv_bfloat16 g_zh[BATCH * LATENT],   g_zl[BATCH * LATENT];
__device__ __nv_bfloat16 g_W1h[1024 * LATENT],   g_W1l[1024 * LATENT]; // [nw1^T; ew1z^T]
__device__ __nv_bfloat16 g_W2h[HIDDEN * HIDDEN], g_W2l[HIDDEN * HIDDEN];
__device__ __nv_bfloat16 g_W3h[MROWS * HIDDEN],  g_W3l[MROWS * HIDDEN];
__device__ __nv_bfloat16 g_h1h[BATCH * HIDDEN],  g_h1l[BATCH * HIDDEN];
__device__ __nv_bfloat16 g_h2h[BATCH * HIDDEN],  g_h2l[BATCH * HIDDEN];
__device__ __half g_Wp16[2 * KDIM * NODE_F];     // ew1 Wi/Wj ^T fp16 [1024][128]
__device__ __half g_nf16[MROWS * NODE_F];        // nf fp16 [6400][128]
__device__ float  g_R [BATCH * KDIM];
__device__ __half g_Ph[MROWS * KDIM];            // fp16 P = nf@Wi + R
__device__ __half g_Qh[MROWS * KDIM];            // fp16 Q = nf@Wj
__device__ int2   g_edge[E_TOTAL];
__device__ __half g_Bh[N2 * KDIM];               // ew2^T fp16 [256 n][512 k]

// ------------------------- helpers ------------------------------------------
__device__ __forceinline__ uint32_t smem_u32(const void* p) {
    uint32_t a;
    asm("{ .reg .u64 t; cvta.to.shared.u64 t, %1; cvt.u32.u64 %0, t; }"
        : "=r"(a) : "l"(p));
    return a;
}
__device__ __forceinline__ void mma16816_f16(float* c, const uint32_t* a,
                                             uint32_t b0, uint32_t b1) {
    asm volatile(
        "mma.sync.aligned.m16n8k16.row.col.f32.f16.f16.f32 "
        "{%0,%1,%2,%3}, {%4,%5,%6,%7}, {%8,%9}, {%0,%1,%2,%3};"
        : "+f"(c[0]), "+f"(c[1]), "+f"(c[2]), "+f"(c[3])
        : "r"(a[0]), "r"(a[1]), "r"(a[2]), "r"(a[3]), "r"(b0), "r"(b1));
}
__device__ __forceinline__ void mma16816_bf(float* c, const uint32_t* a,
                                            uint32_t b0, uint32_t b1) {
    asm volatile(
        "mma.sync.aligned.m16n8k16.row.col.f32.bf16.bf16.f32 "
        "{%0,%1,%2,%3}, {%4,%5,%6,%7}, {%8,%9}, {%0,%1,%2,%3};"
        : "+f"(c[0]), "+f"(c[1]), "+f"(c[2]), "+f"(c[3])
        : "r"(a[0]), "r"(a[1]), "r"(a[2]), "r"(a[3]), "r"(b0), "r"(b1));
}
#define LDM4(r, addr) \
    asm volatile("ldmatrix.sync.aligned.m8n8.x4.shared.b16 {%0,%1,%2,%3}, [%4];" \
        : "=r"((r)[0]), "=r"((r)[1]), "=r"((r)[2]), "=r"((r)[3]) : "r"(addr))
#define CP_ASYNC16(dst, src) \
    asm volatile("cp.async.cg.shared.global [%0], [%1], 16;" \
                 :: "r"(dst), "l"(src) : "memory")
#define CP_COMMIT()  asm volatile("cp.async.commit_group;" ::: "memory")
#define CP_WAIT0()   asm volatile("cp.async.wait_group 0;" ::: "memory")
#define CP_WAIT1()   asm volatile("cp.async.wait_group 1;" ::: "memory")
#define CP_WAIT2()   asm volatile("cp.async.wait_group 2;" ::: "memory")

__device__ __forceinline__ void bf16_split(float v, __nv_bfloat16& h, __nv_bfloat16& l) {
    h = __float2bfloat16(v);
    l = __float2bfloat16(v - __bfloat162float(h));
}

// ---------------------------------------------------------------------------
// Prep bodies (64k x 32n coalesced transpose tiles)
// ---------------------------------------------------------------------------
__device__ __forceinline__ void tsplit_body(const float* __restrict__ src,
                                            __nv_bfloat16* __restrict__ dh,
                                            __nv_bfloat16* __restrict__ dl,
                                            int K, int N, int t, int kt,
                                            float (*sh)[33]) {
    const int k0 = (t % kt) * 64;
    const int n0 = (t / kt) * 32;
    const int tx = threadIdx.x & 31;
    const int ty = threadIdx.x >> 5;
#pragma unroll
    for (int r = ty; r < 64; r += 8)
        sh[r][tx] = src[(size_t)(k0 + r) * N + n0 + tx];
    __syncthreads();
#pragma unroll
    for (int r = ty; r < 32; r += 8) {
        float v0 = sh[2 * tx][r], v1 = sh[2 * tx + 1][r];
        __nv_bfloat16 h0, l0, h1, l1;
        bf16_split(v0, h0, l0); bf16_split(v1, h1, l1);
        const size_t o = ((size_t)(n0 + r) * K + k0 + 2 * tx) >> 1;
        ((__nv_bfloat162*)dh)[o] = __nv_bfloat162(h0, h1);
        ((__nv_bfloat162*)dl)[o] = __nv_bfloat162(l0, l1);
    }
}
__device__ __forceinline__ void tsplit_h_body(const float* __restrict__ src,
                                              __half* __restrict__ dst,
                                              int K, int N, int t, int kt,
                                              float (*sh)[33]) {
    const int k0 = (t % kt) * 64;
    const int n0 = (t / kt) * 32;
    const int tx = threadIdx.x & 31;
    const int ty = threadIdx.x >> 5;
#pragma unroll
    for (int r = ty; r < 64; r += 8)
        sh[r][tx] = src[(size_t)(k0 + r) * N + n0 + tx];
    __syncthreads();
#pragma unroll
    for (int r = ty; r < 32; r += 8) {
        float v0 = sh[2 * tx][r], v1 = sh[2 * tx + 1][r];
        const size_t o = ((size_t)(n0 + r) * K + k0 + 2 * tx) >> 1;
        ((__half2*)dst)[o] = __floats2half2_rn(v0, v1);
    }
}

// side stream: W3 + B + Wp (1728 blocks)
__global__ __launch_bounds__(256)
void prep_side_kernel(const float* __restrict__ nw3, const float* __restrict__ ew1,
                      const float* __restrict__ ew2) {
    __shared__ float sh[64][33];
    int bid = blockIdx.x;
    if (bid < 1600) { tsplit_body(nw3, g_W3h, g_W3l, 512, 6400, bid, 8, sh); return; }
    bid -= 1600;
    if (bid < 64) { tsplit_h_body(ew2, g_Bh, 512, 256, bid, 8, sh); return; }
    bid -= 64;
    if (bid < 32) { tsplit_h_body(ew1 + 256 * 512, g_Wp16, 128, 512, bid, 2, sh); return; }
    bid -= 32;
    { tsplit_h_body(ew1 + 384 * 512, g_Wp16 + 512 * 128, 128, 512, bid, 2, sh); }
}

// main stream: W2, W1 parts, z, edge table — 389 blocks
#define PREPF_BLOCKS (128 + 64 + 64 + 128 + 5)

__global__ __launch_bounds__(256)
void prep_front_kernel(const float* __restrict__ nw2, const float* __restrict__ nw1,
                       const float* __restrict__ ew1, const float* __restrict__ z) {
    __shared__ float sh[64][33];
    int bid = blockIdx.x;
    if (bid < 128)  { tsplit_body(nw2, g_W2h, g_W2l, 512, 512, bid, 8, sh); return; }
    bid -= 128;
    if (bid < 64)   { tsplit_body(nw1, g_W1h, g_W1l, 256, 512, bid, 4, sh); return; }
    bid -= 64;
    if (bid < 64)   { tsplit_body(ew1, g_W1h + 512 * 256, g_W1l + 512 * 256,
                                  256, 512, bid, 4, sh); return; }
    bid -= 64;
    if (bid < 128) {
        const int idx = bid * 256 + threadIdx.x;
        __nv_bfloat16 h, l; bf16_split(z[idx], h, l);
        g_zh[idx] = h; g_zl[idx] = l;
        return;
    }
    bid -= 128;
    {
        const int e = bid * 256 + threadIdx.x;
        if (e < E_TOTAL) {
            int rem = e, i = 0, cnt = MAXN - 1;
            while (rem >= cnt) { rem -= cnt; cnt--; i++; }
            g_edge[e] = make_int2(i, i + 1 + rem);
        }
    }
}

// ---------------------------------------------------------------------------
// 3-pass bf16 split GEMM, 4-deep cp.async pipeline, MT x NT tiles (unchanged).
// ---------------------------------------------------------------------------
template<int K, int EPI, int MT, int NT>
__global__ __launch_bounds__(256)
void gemm3p_kernel(const __nv_bfloat16* __restrict__ Ahi,
                   const __nv_bfloat16* __restrict__ Alo,
                   const __nv_bfloat16* __restrict__ Bhi,
                   const __nv_bfloat16* __restrict__ Blo,
                   const float* __restrict__ bias,
                   const float* __restrict__ bias2,
                   float* __restrict__ out_nodes) {
    extern __shared__ char sm[];
    const uint32_t sb = smem_u32(sm);
    constexpr int NCH  = K / 64;
    constexpr int WNT  = NT / 2;
    constexpr int NBL  = WNT / 16;
    constexpr int MF   = MT / 64;
    constexpr int MGR  = MT / 4;
    constexpr int BHIO = 2 * MT * 144;
    constexpr int BLOO = BHIO + NT * 144;
    constexpr int BUF  = BHIO + 2 * NT * 144;

    const int tid = threadIdx.x, lane = tid & 31, wid = tid >> 5;
    const int g = lane >> 2, qi = lane & 3;
    const int mg = wid >> 1, ng = wid & 1;
    const int m0 = blockIdx.x * MT, n0 = blockIdx.y * NT;

    const uint32_t aHiB = sb + (uint32_t)(mg * MGR + (lane & 15)) * 144
                        + (lane >> 4) * 16;
    const uint32_t aLoB = aHiB + MT * 144;
    const int brow = ng * WNT + ((lane >> 4) & 1) * 8 + (lane & 7);
    const uint32_t bHiB = sb + BHIO + (uint32_t)brow * 144 + ((lane >> 3) & 1) * 16;
    const uint32_t bLoB = bHiB + (BLOO - BHIO);

    auto stage = [&](int c, int buf) {
        const uint32_t bb = sb + buf * BUF;
#pragma unroll
        for (int p = tid; p < MT * 8; p += 256) {
            const int r = p >> 3, pc = p & 7;
            const size_t so = ((size_t)(m0 + r) * K + c * 64) * 2 + pc * 16;
            CP_ASYNC16(bb + r * 144 + pc * 16,            (const char*)Ahi + so);
            CP_ASYNC16(bb + MT * 144 + r * 144 + pc * 16, (const char*)Alo + so);
        }
#pragma unroll
        for (int p = tid; p < NT * 8; p += 256) {
            const int r = p >> 3, pc = p & 7;
            const size_t so = ((size_t)(n0 + r) * K + c * 64) * 2 + pc * 16;
            CP_ASYNC16(bb + BHIO + r * 144 + pc * 16, (const char*)Bhi + so);
            CP_ASYNC16(bb + BLOO + r * 144 + pc * 16, (const char*)Blo + so);
        }
    };

    float acc[MF][2 * NBL][4];
#pragma unroll
    for (int a = 0; a < MF; a++)
#pragma unroll
        for (int b2 = 0; b2 < 2 * NBL; b2++)
#pragma unroll
            for (int u = 0; u < 4; u++) acc[a][b2][u] = 0.0f;

#pragma unroll
    for (int i = 0; i < 3; i++) {
        stage(i, i);
        CP_COMMIT();
    }

    for (int c = 0; c < NCH; c++) {
        const int rem = NCH - 1 - c;
        if (rem >= 2) CP_WAIT2();
        else if (rem == 1) CP_WAIT1();
        else CP_WAIT0();
        __syncthreads();
        if (c + 3 < NCH) {
            stage(c + 3, (c + 3) & 3);
            CP_COMMIT();
        }
        const uint32_t off = (uint32_t)(c & 3) * BUF;
#pragma unroll
        for (int ks = 0; ks < 4; ks++) {
            uint32_t ah[MF][4], al[MF][4];
#pragma unroll
            for (int mf = 0; mf < MF; mf++) {
                LDM4(ah[mf], aHiB + off + mf * (16 * 144) + ks * 32);
                LDM4(al[mf], aLoB + off + mf * (16 * 144) + ks * 32);
            }
#pragma unroll
            for (int nbl = 0; nbl < NBL; nbl++) {
                uint32_t bh[4], bl[4];
                LDM4(bh, bHiB + off + nbl * (16 * 144) + ks * 32);
                LDM4(bl, bLoB + off + nbl * (16 * 144) + ks * 32);
#pragma unroll
                for (int mf = 0; mf < MF; mf++) {
                    float* c0 = acc[mf][2 * nbl];
                    float* c1 = acc[mf][2 * nbl + 1];
                    mma16816_bf(c0, ah[mf], bh[0], bh[1]);
                    mma16816_bf(c1, ah[mf], bh[2], bh[3]);
                    mma16816_bf(c0, al[mf], bh[0], bh[1]);
                    mma16816_bf(c1, al[mf], bh[2], bh[3]);
                    mma16816_bf(c0, ah[mf], bl[0], bl[1]);
                    mma16816_bf(c1, ah[mf], bl[2], bl[3]);
                }
            }
        }
    }

#pragma unroll
    for (int mf = 0; mf < MF; mf++)
#pragma unroll
        for (int nb = 0; nb < 2 * NBL; nb++)
#pragma unroll
            for (int u = 0; u < 4; u++) {
                const int row = mg * MGR + mf * 16 + g + (u >> 1) * 8;
                const int col = ng * WNT + nb * 8 + qi * 2 + (u & 1);
                const int mG = m0 + row, nG = n0 + col;
                float v = acc[mf][nb][u];
                if (EPI == 0) {                       // nw3
                    v += bias[nG];
                    const int node = nG >> 7, f = nG & 127;
                    g_nf16[((size_t)mG * MAXN + node) * NODE_F + f] = __float2half_rn(v);
                    out_nodes[(size_t)mG * 6400 + nG] = 1.0f / (1.0f + expf(-v));
                } else if (EPI == 2) {                // lin1 + R
                    if (nG < 512) {
                        v = fmaxf(v + bias[nG], 0.0f);
                        __nv_bfloat16 h, l; bf16_split(v, h, l);
                        g_h1h[(size_t)mG * 512 + nG] = h;
                        g_h1l[(size_t)mG * 512 + nG] = l;
                    } else {
                        g_R[(size_t)mG * 512 + nG - 512] = v + bias2[nG - 512];
                    }
                } else {                              // lin2
                    v = fmaxf(v + bias[nG], 0.0f);
                    __nv_bfloat16 h, l; bf16_split(v, h, l);
                    g_h2h[(size_t)mG * 512 + nG] = h;
                    g_h2l[(size_t)mG * 512 + nG] = l;
                }
            }
}

// ---------------------------------------------------------------------------
// Single-pass fp16 GEMM for P/Q, double-buffered (unchanged). Grid (50,16).
// ---------------------------------------------------------------------------
#define G1_A   0
#define G1_B   18432
#define G1_BUF 27648
#define G1_TOT 55296

__global__ __launch_bounds__(256)
void gemm1p_kernel() {
    extern __shared__ char sm[];
    const uint32_t sb = smem_u32(sm);
    const int tid = threadIdx.x, lane = tid & 31, wid = tid >> 5;
    const int g = lane >> 2, qi = lane & 3;
    const int mg = wid >> 1, ng = wid & 1;
    const int m0 = blockIdx.x * 128, n0 = blockIdx.y * 64;

    const uint32_t aAB = sb + G1_A + (uint32_t)(mg * 32 + (lane & 15)) * 144
                       + (lane >> 4) * 16;
    const int brow = ng * 32 + ((lane >> 4) & 1) * 8 + (lane & 7);
    const uint32_t aBB = sb + G1_B + (uint32_t)brow * 144 + ((lane >> 3) & 1) * 16;

    auto stage = [&](int c, int buf) {
        const uint32_t bb = sb + buf * G1_BUF;
#pragma unroll
        for (int p = tid; p < 1024; p += 256) {
            const int r = p >> 3, pc = p & 7;
            CP_ASYNC16(bb + G1_A + r * 144 + pc * 16,
                       (const char*)g_nf16 + ((size_t)(m0 + r) * 128 + c * 64) * 2 + pc * 16);
        }
#pragma unroll
        for (int p = tid; p < 512; p += 256) {
            const int r = p >> 3, pc = p & 7;
            CP_ASYNC16(bb + G1_B + r * 144 + pc * 16,
                       (const char*)g_Wp16 + ((size_t)(n0 + r) * 128 + c * 64) * 2 + pc * 16);
        }
    };

    float acc[2][4][4];
#pragma unroll
    for (int a = 0; a < 2; a++)
#pragma unroll
        for (int b2 = 0; b2 < 4; b2++)
#pragma unroll
            for (int u = 0; u < 4; u++) acc[a][b2][u] = 0.0f;

    stage(0, 0);
    CP_COMMIT();
    stage(1, 1);
    CP_COMMIT();

    for (int c = 0; c < 2; c++) {
        if (c == 0) CP_WAIT1(); else CP_WAIT0();
        __syncthreads();
        const uint32_t off = (uint32_t)(c & 1) * G1_BUF;
#pragma unroll
        for (int ks = 0; ks < 4; ks++) {
            uint32_t a0[4], a1[4];
            LDM4(a0, aAB + off + ks * 32);
            LDM4(a1, aAB + off + 16 * 144 + ks * 32);
#pragma unroll
            for (int nb = 0; nb < 2; nb++) {
                uint32_t bh[4];
                LDM4(bh, aBB + off + nb * (16 * 144) + ks * 32);
                mma16816_f16(acc[0][2 * nb],     a0, bh[0], bh[1]);
                mma16816_f16(acc[1][2 * nb],     a1, bh[0], bh[1]);
                mma16816_f16(acc[0][2 * nb + 1], a0, bh[2], bh[3]);
                mma16816_f16(acc[1][2 * nb + 1], a1, bh[2], bh[3]);
            }
        }
    }

#pragma unroll
    for (int mf = 0; mf < 2; mf++)
#pragma unroll
        for (int nb = 0; nb < 4; nb++)
#pragma unroll
            for (int u = 0; u < 4; u++) {
                const int row = mg * 32 + mf * 16 + g + (u >> 1) * 8;
                const int col = ng * 32 + nb * 8 + qi * 2 + (u & 1);
                const int mG = m0 + row, n2 = n0 + col;
                float v = acc[mf][nb][u];
                const int mat = n2 >> 9, nc = n2 & 511;
                if (!mat) {
                    v += g_R[(size_t)(mG / MAXN) * KDIM + nc];
                    g_Ph[(size_t)mG * KDIM + nc] = __float2half_rn(v);
                } else {
                    g_Qh[(size_t)mG * KDIM + nc] = __float2half_rn(v);
                }
            }
}

// ---------------------------------------------------------------------------
// Edge kernel v2: 256 threads, 64-edge x 256-N tiles, 2 CTAs/SM.
// e1 = relu(P_i + Q_j) fp16; single-pass fp16 HMMA. B+PQ double-buffered.
// 8 warps = 2 m-groups (32 edges) x 4 n-groups (64 N).
// PQ_STRIDE = 144 (16B aligned: uint4 loads at node*144 are legal).
// ---------------------------------------------------------------------------
#define TILE_E    64
#define BN_STRIDE 144
#define PQ_STRIDE 144
#define BBUF_SZ   36864            // 256*144
#define OFF_P     73728            // + buf*14400 ; Q at +7200
#define PQBUF_SZ  14400
#define OFF_AHI   102528           // 64*144 = 9216
#define OFF_EB2   111744
#define OFF_EW3   112768
#define OFF_RED   113792           // 4*64*4 = 1024
#define EDGE_SMEM 114816           // <= 116736 (228KB/2) -> 2 CTAs/SM

__device__ __forceinline__ void stage_B(uint32_t sb, int c, int bufoff, int tid) {
#pragma unroll
    for (int p = tid; p < 2048; p += 256) {
        const int r  = p >> 3;
        const int pc = p & 7;
        const char* src = (const char*)g_Bh + r * 1024 + c * 128 + pc * 16;
        CP_ASYNC16(sb + bufoff + r * BN_STRIDE + pc * 16, src);
    }
}
__device__ __forceinline__ void stage_PQ(uint32_t sb, int b, int c, int buf, int tid) {
    for (int p = tid; p < 800; p += 256) {
        const int mat = p >= 400;
        const int s2  = p - mat * 400;
        const int r   = s2 >> 3;
        const int pc  = s2 & 7;
        const char* src = (const char*)(mat ? g_Qh : g_Ph)
                        + (size_t)(b * MAXN + r) * 1024 + c * 128 + pc * 16;
        CP_ASYNC16(sb + OFF_P + buf * PQBUF_SZ + mat * 7200 + r * PQ_STRIDE + pc * 16,
                   src);
    }
}

__global__ __launch_bounds__(256, 2)
void edge_mma_kernel(const float* __restrict__ eb2g,
                     const float* __restrict__ ew3g,
                     const float* __restrict__ eb3g,
                     float* __restrict__ out_edges) {
    extern __shared__ char sm[];
    const uint32_t sb = smem_u32(sm);
    const int tid  = threadIdx.x;
    const int lane = tid & 31, wid = tid >> 5;
    const int g    = lane >> 2, qi = lane & 3;
    const int mg   = wid >> 2,  ng = wid & 3;    // 2 m-groups x 4 n-groups
    const int b      = blockIdx.y;
    const int e_base = blockIdx.x * TILE_E;

    ((float*)(sm + OFF_EB2))[tid] = eb2g[tid];
    ((float*)(sm + OFF_EW3))[tid] = ew3g[tid];

    // build role: thread -> (edge row mb 0..63, 16-wide k group)
    const int mb = tid >> 2;
    const int kk = (tid & 3) * 16;
    const int2 ijb = g_edge[min(e_base + mb, E_TOTAL - 1)];
    const int pOff = ijb.x * PQ_STRIDE + kk * 2;
    const int qOff = 7200 + ijb.y * PQ_STRIDE + kk * 2;
    char* ahiW = sm + OFF_AHI + mb * BN_STRIDE + kk * 2;

    const uint32_t aoff = (uint32_t)(mg * 32 + (lane & 15)) * BN_STRIDE
                        + (uint32_t)(lane >> 4) * 16;
    const uint32_t aHi = sb + OFF_AHI + aoff;
    const int brow  = ng * 64 + ((lane >> 4) & 1) * 8 + (lane & 7);
    const uint32_t boff = (uint32_t)brow * BN_STRIDE + ((lane >> 3) & 1) * 16;

    stage_B(sb, 0, 0, tid);
    stage_PQ(sb, b, 0, 0, tid);
    CP_COMMIT();

    float acc[2][8][4];
#pragma unroll
    for (int mt = 0; mt < 2; mt++)
#pragma unroll
        for (int f = 0; f < 8; f++)
#pragma unroll
            for (int u = 0; u < 4; u++) acc[mt][f][u] = 0.0f;

    for (int c = 0; c < 8; c++) {
        CP_WAIT0();
        __syncthreads();

        if (c + 1 < 8) {
            stage_B(sb, c + 1, ((c + 1) & 1) * BBUF_SZ, tid);
            stage_PQ(sb, b, c + 1, (c + 1) & 1, tid);
            CP_COMMIT();
        }

        // ---- build e1 chunk: 16 fp16 values/thread ----
        {
            const char* base = sm + OFF_P + (c & 1) * PQBUF_SZ;
            const uint4 pa  = *(const uint4*)(base + pOff);
            const uint4 pb2 = *(const uint4*)(base + pOff + 16);
            const uint4 qa  = *(const uint4*)(base + qOff);
            const uint4 qb2 = *(const uint4*)(base + qOff + 16);
            const __half2 z2 = __float2half2_rn(0.0f);
            uint32_t pw[8] = {pa.x, pa.y, pa.z, pa.w, pb2.x, pb2.y, pb2.z, pb2.w};
            uint32_t qw[8] = {qa.x, qa.y, qa.z, qa.w, qb2.x, qb2.y, qb2.z, qb2.w};
            uint32_t o[8];
#pragma unroll
            for (int x = 0; x < 8; x++) {
                __half2 r = __hmax2(__hadd2(*(__half2*)&pw[x], *(__half2*)&qw[x]), z2);
                o[x] = *(uint32_t*)&r;
            }
            *(uint4*)(ahiW)      = make_uint4(o[0], o[1], o[2], o[3]);
            *(uint4*)(ahiW + 16) = make_uint4(o[4], o[5], o[6], o[7]);
        }
        __syncthreads();

        // ---- single-pass fp16 MMA ----
        const uint32_t bbase = sb + (c & 1) * BBUF_SZ + boff;
#pragma unroll
        for (int ks = 0; ks < 4; ks++) {
            uint32_t a0[4], a1[4];
            LDM4(a0, aHi + ks * 32);
            LDM4(a1, aHi + 16 * BN_STRIDE + ks * 32);
#pragma unroll
            for (int fp = 0; fp < 4; fp++) {
                uint32_t bh[4];
                LDM4(bh, bbase + fp * (16 * BN_STRIDE) + ks * 32);
                mma16816_f16(acc[0][2*fp],   a0, bh[0], bh[1]);
                mma16816_f16(acc[1][2*fp],   a1, bh[0], bh[1]);
                mma16816_f16(acc[0][2*fp+1], a0, bh[2], bh[3]);
                mma16816_f16(acc[1][2*fp+1], a1, bh[2], bh[3]);
            }
        }
    }

    // ---- epilogue ----
    const float* eb2s = (const float*)(sm + OFF_EB2);
    const float* ew3s = (const float*)(sm + OFF_EW3);
    int rowm[4];
    rowm[0] = mg * 32 + g;      rowm[1] = mg * 32 + 8 + g;
    rowm[2] = mg * 32 + 16 + g; rowm[3] = mg * 32 + 24 + g;
    float pr[4] = {0.f, 0.f, 0.f, 0.f};
#pragma unroll
    for (int f = 0; f < 8; f++) {
        const int n0 = ng * 64 + f * 8 + qi * 2;
        const float b0 = eb2s[n0], b1 = eb2s[n0 + 1];
        const float w0 = ew3s[n0], w1 = ew3s[n0 + 1];
#pragma unroll
        for (int mt = 0; mt < 2; mt++) {
            pr[mt * 2 + 0] += fmaxf(acc[mt][f][0] + b0, 0.0f) * w0 +
                              fmaxf(acc[mt][f][1] + b1, 0.0f) * w1;
            pr[mt * 2 + 1] += fmaxf(acc[mt][f][2] + b0, 0.0f) * w0 +
                              fmaxf(acc[mt][f][3] + b1, 0.0f) * w1;
        }
    }
#pragma unroll
    for (int j = 0; j < 4; j++) {
        pr[j] += __shfl_xor_sync(0xffffffffu, pr[j], 1);
        pr[j] += __shfl_xor_sync(0xffffffffu, pr[j], 2);
    }
    float* red = (float*)(sm + OFF_RED);
    if (qi == 0) {
#pragma unroll
        for (int j = 0; j < 4; j++) red[ng * TILE_E + rowm[j]] = pr[j];
    }
    __syncthreads();
    if (tid < TILE_E) {
        int e = e_base + tid;
        if (e < E_TOTAL) {
            float s = red[tid] + red[64 + tid] + red[128 + tid] + red[192 + tid]
                    + eb3g[0];
            out_edges[(size_t)b * E_TOTAL + e] = 1.0f / (1.0f + expf(-s));
        }
    }
}

// ---------------------------------------------------------------------------
extern "C" void kernel_launch(void* const* d_in, const int* in_sizes, int n_in,
                              void* d_out, int out_size) {
    const float* z   = (const float*)d_in[0];
    const float* nw1 = (const float*)d_in[1];
    const float* nb1 = (const float*)d_in[2];
    const float* nw2 = (const float*)d_in[3];
    const float* nb2 = (const float*)d_in[4];
    const float* nw3 = (const float*)d_in[5];
    const float* nb3 = (const float*)d_in[6];
    const float* ew1 = (const float*)d_in[7];
    const float* eb1 = (const float*)d_in[8];
    const float* ew2 = (const float*)d_in[9];
    const float* eb2 = (const float*)d_in[10];
    const float* ew3 = (const float*)d_in[11];
    const float* eb3 = (const float*)d_in[12];

    float* out_nodes = (float*)d_out;
    float* out_edges = (float*)d_out + NODE_OUT;

    __nv_bfloat16 *zh, *zl, *W1h, *W1l, *W2h, *W2l, *W3h, *W3l;
    __nv_bfloat16 *h1h, *h1l, *h2h, *h2l;
    cudaGetSymbolAddress((void**)&zh,  g_zh);  cudaGetSymbolAddress((void**)&zl,  g_zl);
    cudaGetSymbolAddress((void**)&W1h, g_W1h); cudaGetSymbolAddress((void**)&W1l, g_W1l);
    cudaGetSymbolAddress((void**)&W2h, g_W2h); cudaGetSymbolAddress((void**)&W2l, g_W2l);
    cudaGetSymbolAddress((void**)&W3h, g_W3h); cudaGetSymbolAddress((void**)&W3l, g_W3l);
    cudaGetSymbolAddress((void**)&h1h, g_h1h); cudaGetSymbolAddress((void**)&h1l, g_h1l);
    cudaGetSymbolAddress((void**)&h2h, g_h2h); cudaGetSymbolAddress((void**)&h2l, g_h2l);

    constexpr int GS_M64  = 4 * (2 * 64 * 144 + 2 * 32 * 144);   // 110592
    constexpr int GS_M128 = 4 * (2 * 128 * 144 + 2 * 32 * 144);  // 184320

    static bool init_done = false;
    static cudaStream_t s2;
    static cudaEvent_t evFork, evJoin;
    if (!init_done) {
        cudaStreamCreateWithFlags(&s2, cudaStreamNonBlocking);
        cudaEventCreateWithFlags(&evFork, cudaEventDisableTiming);
        cudaEventCreateWithFlags(&evJoin, cudaEventDisableTiming);
        cudaFuncSetAttribute(edge_mma_kernel,
                             cudaFuncAttributeMaxDynamicSharedMemorySize, EDGE_SMEM);
        cudaFuncSetAttribute(gemm3p_kernel<256, 2, 64, 32>,
                             cudaFuncAttributeMaxDynamicSharedMemorySize, GS_M64);
        cudaFuncSetAttribute(gemm3p_kernel<512, 3, 64, 32>,
                             cudaFuncAttributeMaxDynamicSharedMemorySize, GS_M64);
        cudaFuncSetAttribute(gemm3p_kernel<512, 0, 128, 32>,
                             cudaFuncAttributeMaxDynamicSharedMemorySize, GS_M128);
        cudaFuncSetAttribute(gemm1p_kernel,
                             cudaFuncAttributeMaxDynamicSharedMemorySize, G1_TOT);
        init_done = true;
    }

    // fork: W3/B/Wp transposes on side stream (needed from nw3/pq/edge on)
    cudaEventRecord(evFork, 0);
    cudaStreamWaitEvent(s2, evFork, 0);
    prep_side_kernel<<<1728, 256, 0, s2>>>(nw3, ew1, ew2);
    cudaEventRecord(evJoin, s2);

    // main stream
    prep_front_kernel<<<PREPF_BLOCKS, 256>>>(nw2, nw1, ew1, z);
    gemm3p_kernel<256, 2, 64, 32><<<dim3(2, 32), 256, GS_M64>>>(
        zh, zl, W1h, W1l, nb1, eb1, nullptr);
    gemm3p_kernel<512, 3, 64, 32><<<dim3(2, 16), 256, GS_M64>>>(
        h1h, h1l, W2h, W2l, nb2, nullptr, nullptr);

    cudaStreamWaitEvent(0, evJoin, 0);
    gemm3p_kernel<512, 0, 128, 32><<<dim3(1, 200), 256, GS_M128>>>(
        h2h, h2l, W3h, W3l, nb3, nullptr, out_nodes);
    gemm1p_kernel<<<dim3(MROWS / 128, 16), 256, G1_TOT>>>();

    // dominant edge GEMM: 64-edge tiles, 2 CTAs/SM
    edge_mma_kernel<<<dim3((E_TOTAL + TILE_E - 1) / TILE_E, BATCH),
                      256, EDGE_SMEM>>>(eb2, ew3, eb3, out_edges);
}